// round 9
// baseline (speedup 1.0000x reference)
#include <cuda_runtime.h>
#include <cuda_bf16.h>
#include <cstdint>

// ---------------- problem constants ----------------
#define NIMG   8192
#define C1     20
#define C2     50
#define P1PIX  196          // 14*14 pooled pixels after stage 1
#define LIN_IN 1250
#define NWRD   40           // ceil(1250/32)
#define LIN_OUT 500
#define NCLS   10
#define IMGB   16           // images per k5 block

// ---------------- device scratch ----------------
__device__ float        g_part[NIMG * C1];
__device__ float        g_mean[C1];
__device__ unsigned int g_b1p[NIMG * P1PIX];        // stage-1 bits, 20/pixel
__device__ unsigned int g_w2p[C2 * 25];             // conv2 positive-sign masks
__device__ unsigned int g_wpl[LIN_OUT * NWRD];      // linear positive-sign bitmask
__device__ float        g_alphal[LIN_OUT];
__device__ uint2        g_s2p[NIMG * NWRD];         // stage-2 (sp, sn) bit words
__device__ unsigned long long g_swd_stage[C1 * 26]; // duplicated conv1 weights (staging)

// ---------------- constant-memory conv1 means ----------------
__constant__ float c_mean[C1];

// ---------------- f32x2 helpers ----------------
__device__ __forceinline__ unsigned long long pack2(float lo, float hi) {
    unsigned long long r;
    asm("mov.b64 %0, {%1, %2};" : "=l"(r) : "f"(lo), "f"(hi));
    return r;
}
__device__ __forceinline__ void unpack2(unsigned long long v, float& lo, float& hi) {
    asm("mov.b64 {%0, %1}, %2;" : "=f"(lo), "=f"(hi) : "l"(v));
}
__device__ __forceinline__ unsigned long long fma2(unsigned long long a,
                                                   unsigned long long b,
                                                   unsigned long long c) {
    unsigned long long d;
    asm("fma.rn.f32x2 %0, %1, %2, %3;" : "=l"(d) : "l"(a), "l"(b), "l"(c));
    return d;
}

// ================= kw: weight preprocessing (all-in-one) =================
__global__ void kw_pack(const float* __restrict__ w1, const float* __restrict__ w2,
                        const float* __restrict__ wl) {
    int gid = blockIdx.x * blockDim.x + threadIdx.x;
    int stride = gridDim.x * blockDim.x;
    // conv1 duplicated-weight staging (index 25 of each row left untouched/unused)
    for (int i = gid; i < C1 * 26; i += stride) {
        int c = i / 26, p = i % 26;
        float v = (p < 25) ? w1[c * 25 + p] : 0.f;
        g_swd_stage[i] = pack2(v, v);
    }
    // conv2 positive masks (weights are never exactly 0)
    for (int i = gid; i < C2 * 25; i += stride) {
        int oc = i / 25, p = i % 25;
        unsigned wp = 0;
        for (int ic = 0; ic < C1; ic++)
            if (w2[(oc * C1 + ic) * 25 + p] > 0.f) wp |= (1u << ic);
        g_w2p[i] = wp;
    }
    // linear sign bitmask
    for (int i = gid; i < LIN_OUT * NWRD; i += stride) {
        int oc = i / NWRD, w = i % NWRD;
        unsigned bits = 0;
        for (int j = 0; j < 32; j++) {
            int k = w * 32 + j;
            if (k < LIN_IN && wl[oc * LIN_IN + k] > 0.f) bits |= (1u << j);
        }
        g_wpl[i] = bits;
    }
    // alpha: one warp per output row
    for (int i = gid; i < LIN_OUT * 32; i += stride) {
        int oc = i >> 5, lane = i & 31;
        float s = 0.f;
        for (int k = lane; k < LIN_IN; k += 32) s += fabsf(wl[oc * LIN_IN + k]);
#pragma unroll
        for (int off = 16; off > 0; off >>= 1)
            s += __shfl_down_sync(0xffffffffu, s, off);
        if (lane == 0) g_alphal[oc] = s * (1.f / (float)LIN_IN);
    }
}

// ================= k1: per-image conv1 channel sums via window sums =================
__global__ void k1_stats(const float* __restrict__ x, const float* __restrict__ w1) {
    int img = blockIdx.x, t = threadIdx.x;         // 256 threads
    __shared__ float sR[32 * 5];
    __shared__ float sS[25];
    __shared__ float sw[C1 * 25];
    for (int i = t; i < C1 * 25; i += 256) sw[i] = w1[i];
    int warp = t >> 5, lane = t & 31;
    for (int r = warp; r < 32; r += 8) {
        float v = x[img * 1024 + r * 32 + lane];
        float p = v;
#pragma unroll
        for (int off = 1; off < 32; off <<= 1) {
            float o = __shfl_up_sync(0xffffffffu, p, off);
            if (lane >= off) p += o;
        }
        float lo = __shfl_up_sync(0xffffffffu, p, 1);
        if (lane == 0) lo = 0.f;
        float hi = __shfl_sync(0xffffffffu, p, (lane + 27) & 31);
        if (lane < 5) sR[r * 5 + lane] = hi - lo;
    }
    __syncthreads();
    if (t < 25) {
        int ky = t / 5, kx = t % 5;
        float s = 0.f;
        for (int r = ky; r < ky + 28; r++) s += sR[r * 5 + kx];
        sS[t] = s;
    }
    __syncthreads();
    if (t < C1) {
        float a = 0.f;
#pragma unroll
        for (int p = 0; p < 25; p++) a += sw[t * 25 + p] * sS[p];
        g_part[img * C1 + t] = a;
    }
}

// ================= k2: deterministic channel-mean reduction =================
__global__ void k2_mean() {
    int c = blockIdx.x, t = threadIdx.x;
    __shared__ float red[256];
    float s = 0.f;
    for (int i = t; i < NIMG; i += 256) s += g_part[i * C1 + c];
    red[t] = s;
    __syncthreads();
    for (int o = 128; o > 0; o >>= 1) {
        if (t < o) red[t] += red[t + o];
        __syncthreads();
    }
    if (t == 0) g_mean[c] = red[0] * (1.0f / (8192.f * 784.f));
}

// ================= k3: conv1 + threshold + pool + sign, FFMA2, smem LDS.128 weights =================
#define K3_T 416
__global__ void __launch_bounds__(K3_T, 2) k3_conv1(const float* __restrict__ x) {
    __shared__ float sx[2048];               // 2 images
    __shared__ __align__(16) unsigned long long swd[C1 * 26];  // (w,w) pairs, stride 26
    int t = threadIdx.x;
    int base = blockIdx.x * 2048;
    for (int i = t; i < 2048; i += K3_T) sx[i] = x[base + i];
    for (int i = t; i < C1 * 26; i += K3_T) swd[i] = g_swd_stage[i];
    __syncthreads();
    if (t < 392) {
        int il = t / 196, pp = t % 196;
        int py = pp / 14, px = pp % 14;
        const float* sxi = sx + il * 1024;
        // packed pairs: P[r][k] = (win[r][k], win[r][k+1])  — positions dx=0 / dx=1
        unsigned long long P[6][5];
#pragma unroll
        for (int r = 0; r < 6; r++) {
            float c0 = sxi[(py * 2 + r) * 32 + px * 2 + 0];
            float c1 = sxi[(py * 2 + r) * 32 + px * 2 + 1];
            float c2 = sxi[(py * 2 + r) * 32 + px * 2 + 2];
            float c3 = sxi[(py * 2 + r) * 32 + px * 2 + 3];
            float c4 = sxi[(py * 2 + r) * 32 + px * 2 + 4];
            float c5 = sxi[(py * 2 + r) * 32 + px * 2 + 5];
            P[r][0] = pack2(c0, c1);
            P[r][1] = pack2(c1, c2);
            P[r][2] = pack2(c2, c3);
            P[r][3] = pack2(c3, c4);
            P[r][4] = pack2(c4, c5);
        }
        unsigned int bits = 0;
#pragma unroll
        for (int c = 0; c < C1; c++) {
            // 12 x LDS.128 + 1 x LDS.64 (c*26*8 = 208B, 16B-aligned); broadcast, N=1
            const ulonglong2* wc2 = reinterpret_cast<const ulonglong2*>(&swd[c * 26]);
            unsigned long long a0 = 0ull, a1 = 0ull;   // dy=0 / dy=1, dx in halves
#pragma unroll
            for (int q = 0; q < 12; q++) {
                ulonglong2 w = wc2[q];
                int p0 = 2 * q, p1 = 2 * q + 1;
                a0 = fma2(P[p0 / 5][p0 % 5], w.x, a0);
                a1 = fma2(P[p0 / 5 + 1][p0 % 5], w.x, a1);
                a0 = fma2(P[p1 / 5][p1 % 5], w.y, a0);
                a1 = fma2(P[p1 / 5 + 1][p1 % 5], w.y, a1);
            }
            {
                unsigned long long w24 = swd[c * 26 + 24];
                a0 = fma2(P[4][4], w24, a0);
                a1 = fma2(P[5][4], w24, a1);
            }
            float f00, f01, f10, f11;
            unpack2(a0, f00, f01);
            unpack2(a1, f10, f11);
            float m = fmaxf(fmaxf(f00, f01), fmaxf(f10, f11));
            if (m > c_mean[c]) bits |= (1u << c);
        }
        g_b1p[(blockIdx.x * 2 + il) * P1PIX + pp] = bits;
    }
}

// ================= k4: XNOR conv2 + pool + sign (R7 single-image version) =================
__global__ void __launch_bounds__(256) k4_conv2() {
    __shared__ __align__(8) unsigned int sb[P1PIX];
    __shared__ unsigned int sw2[C2 * 25];
    __shared__ int spc[P1PIX];
    __shared__ int sS[100];
    __shared__ signed char s2b[1280];
    int img = blockIdx.x, t = threadIdx.x;
    for (int i = t; i < P1PIX; i += 256) {
        unsigned v = g_b1p[img * P1PIX + i];
        sb[i] = v;
        spc[i] = __popc(v);
    }
    for (int i = t; i < C2 * 25; i += 256) sw2[i] = g_w2p[i];
    __syncthreads();
    if (t < 100) {
        int py = t / 10, px = t % 10;
        int s = 0;
#pragma unroll
        for (int ky = 0; ky < 5; ky++)
#pragma unroll
            for (int kx = 0; kx < 5; kx++)
                s += spc[(py + ky) * 14 + px + kx];
        sS[t] = s;
    }
    __syncthreads();
    if (t < 250) {
        int pp = t / 10, ocg = t % 10;       // pixel pp cached across 5 ocs
        int py = pp / 5, px = pp % 5;
        unsigned int win[6][6];
#pragma unroll
        for (int r = 0; r < 6; r++) {
            const uint2* row = reinterpret_cast<const uint2*>(sb + (py * 2 + r) * 14 + px * 2);
            uint2 v0 = row[0], v1 = row[1], v2 = row[2];
            win[r][0] = v0.x; win[r][1] = v0.y;
            win[r][2] = v1.x; win[r][3] = v1.y;
            win[r][4] = v2.x; win[r][5] = v2.y;
        }
        int b00 = sS[(2 * py) * 10 + 2 * px];
        int b01 = sS[(2 * py) * 10 + 2 * px + 1];
        int b10 = sS[(2 * py + 1) * 10 + 2 * px];
        int b11 = sS[(2 * py + 1) * 10 + 2 * px + 1];
#pragma unroll 1
        for (int j = 0; j < 5; j++) {
            int oc = ocg * 5 + j;
            const unsigned int* wr = &sw2[oc * 25];
            int A0 = 0, A1 = 0, A2 = 0, A3 = 0;
#pragma unroll
            for (int ky = 0; ky < 5; ky++) {
                unsigned w0 = wr[ky * 5 + 0], w1 = wr[ky * 5 + 1], w2 = wr[ky * 5 + 2];
                unsigned w3 = wr[ky * 5 + 3], w4 = wr[ky * 5 + 4];
                A0 += (__popc(win[ky][0] & w0) + __popc(win[ky][1] & w1))
                    + (__popc(win[ky][2] & w2) + __popc(win[ky][3] & w3))
                    +  __popc(win[ky][4] & w4);
                A1 += (__popc(win[ky][1] & w0) + __popc(win[ky][2] & w1))
                    + (__popc(win[ky][3] & w2) + __popc(win[ky][4] & w3))
                    +  __popc(win[ky][5] & w4);
                A2 += (__popc(win[ky + 1][0] & w0) + __popc(win[ky + 1][1] & w1))
                    + (__popc(win[ky + 1][2] & w2) + __popc(win[ky + 1][3] & w3))
                    +  __popc(win[ky + 1][4] & w4);
                A3 += (__popc(win[ky + 1][1] & w0) + __popc(win[ky + 1][2] & w1))
                    + (__popc(win[ky + 1][3] & w2) + __popc(win[ky + 1][4] & w3))
                    +  __popc(win[ky + 1][5] & w4);
            }
            int a0 = 2 * A0 - b00;
            int a1 = 2 * A1 - b01;
            int a2 = 2 * A2 - b10;
            int a3 = 2 * A3 - b11;
            int best = max(max(a0, a1), max(a2, a3));
            s2b[oc * 25 + pp] = (signed char)((best > 0) - (best < 0));
        }
    }
    for (int i = 1250 + t; i < 1280; i += 256) s2b[i] = 0;
    __syncthreads();
    int lane = t & 31;
#pragma unroll
    for (int it = 0; it < 5; it++) {
        int idx = it * 256 + t;
        int v = s2b[idx];
        unsigned bp = __ballot_sync(0xffffffffu, v > 0);
        unsigned bn = __ballot_sync(0xffffffffu, v < 0);
        if (lane == 0) g_s2p[img * NWRD + (idx >> 5)] = make_uint2(bp, bn);
    }
}

// ================= k5: popcount ternary linear + alpha + clip + fused fc =================
__global__ void __launch_bounds__(256) k5_linear(const float* __restrict__ fcw,
                                                 const float* __restrict__ fcb,
                                                 float* __restrict__ out) {
    __shared__ __align__(16) uint4 s2[IMGB * (NWRD / 2)];  // {sp_w, sn_w, sp_w+1, sn_w+1}
    __shared__ int   sD[IMGB];            // PSP - PSN per image
    __shared__ float sa[IMGB * LIN_OUT];  // clipped activations, 32 KB
    int blk = blockIdx.x, t = threadIdx.x;
    int n0 = blk * IMGB;
    const uint4* src = reinterpret_cast<const uint4*>(g_s2p + (size_t)n0 * NWRD);
    for (int i = t; i < IMGB * (NWRD / 2); i += 256) s2[i] = src[i];
    __syncthreads();
    if (t < IMGB) {
        int d = 0;
#pragma unroll
        for (int w = 0; w < NWRD / 2; w++) {
            uint4 s = s2[t * (NWRD / 2) + w];
            d += (__popc(s.x) - __popc(s.y)) + (__popc(s.z) - __popc(s.w));
        }
        sD[t] = d;
    }
    __syncthreads();
    for (int oc = t; oc < LIN_OUT; oc += 256) {
        float al = g_alphal[oc];
        const uint2* wr = reinterpret_cast<const uint2*>(g_wpl + oc * NWRD);
        int acc[IMGB];
#pragma unroll
        for (int n = 0; n < IMGB; n++) acc[n] = 0;
#pragma unroll 2
        for (int w = 0; w < NWRD / 2; w++) {
            uint2 wv = wr[w];
#pragma unroll
            for (int n = 0; n < IMGB; n++) {
                uint4 s = s2[n * (NWRD / 2) + w];
                acc[n] += (__popc(s.x & wv.x) - __popc(s.y & wv.x))
                        + (__popc(s.z & wv.y) - __popc(s.w & wv.y));
            }
        }
#pragma unroll
        for (int n = 0; n < IMGB; n++) {
            float v = (float)(2 * acc[n] - sD[n]) * al;
            v = fminf(1.f, fmaxf(-1.f, v));
            sa[n * LIN_OUT + oc] = v;
        }
    }
    __syncthreads();
    // fused fc: 16 images x 10 classes
    for (int i = t; i < IMGB * NCLS; i += 256) {
        int n = i / NCLS, cls = i % NCLS;
        const float* a = sa + n * LIN_OUT;
        const float* w = fcw + cls * LIN_OUT;
        float acc = 0.f;
#pragma unroll 4
        for (int k = 0; k < LIN_OUT; k++) acc += a[k] * w[k];
        out[(n0 + n) * NCLS + cls] = acc + fcb[cls];
    }
}

// ================= launch =================
extern "C" void kernel_launch(void* const* d_in, const int* in_sizes, int n_in,
                              void* d_out, int out_size) {
    const float* x   = (const float*)d_in[0];
    const float* w1  = (const float*)d_in[1];
    const float* w2  = (const float*)d_in[2];
    const float* wl  = (const float*)d_in[3];
    const float* fcw = (const float*)d_in[4];
    const float* fcb = (const float*)d_in[5];
    float* out = (float*)d_out;

    kw_pack  <<<256, 256>>>(w1, w2, wl);
    k1_stats <<<NIMG, 256>>>(x, w1);
    k2_mean  <<<C1, 256>>>();

    // stage means -> constant memory (graph-capturable D2D memcpy node)
    void* p_mean = nullptr;
    cudaGetSymbolAddress(&p_mean, g_mean);
    cudaMemcpyToSymbolAsync(c_mean, p_mean, C1 * sizeof(float), 0,
                            cudaMemcpyDeviceToDevice, 0);

    k3_conv1 <<<NIMG / 2, K3_T>>>(x);
    k4_conv2 <<<NIMG, 256>>>();
    k5_linear<<<NIMG / IMGB, 256>>>(fcw, fcb, out);
}

// round 10
// speedup vs baseline: 1.2013x; 1.2013x over previous
#include <cuda_runtime.h>
#include <cuda_bf16.h>
#include <cstdint>

// ---------------- problem constants ----------------
#define NIMG   8192
#define C1     20
#define C2     50
#define P1PIX  196          // 14*14 pooled pixels after stage 1
#define LIN_IN 1250
#define NWRD   40           // ceil(1250/32)
#define LIN_OUT 500
#define NCLS   10
#define IMGB   16           // images per k5 block

// ---------------- device scratch ----------------
__device__ float        g_part[NIMG * C1];
__device__ float        g_mean[C1];
__device__ unsigned int g_b1p[NIMG * P1PIX];        // stage-1 bits, 20/pixel
__device__ ulonglong2   g_w2pk[C2 * 5];             // conv2 packed masks {W3,W2} per (oc,ky)
__device__ unsigned int g_wpl[LIN_OUT * NWRD];      // linear positive-sign bitmask
__device__ float        g_alphal[LIN_OUT];
__device__ uint2        g_s2p[NIMG * NWRD];         // stage-2 (sp, sn) bit words
__device__ unsigned long long g_swd_stage[C1 * 26]; // duplicated conv1 weights (staging)

// ---------------- constant-memory conv1 params ----------------
__constant__ unsigned long long c_swd[C1 * 26];     // (w,w) pairs, stride 26 (208B, 16-aligned)
__constant__ float c_mean[C1];

// ---------------- f32x2 helpers ----------------
__device__ __forceinline__ unsigned long long pack2(float lo, float hi) {
    unsigned long long r;
    asm("mov.b64 %0, {%1, %2};" : "=l"(r) : "f"(lo), "f"(hi));
    return r;
}
__device__ __forceinline__ void unpack2(unsigned long long v, float& lo, float& hi) {
    asm("mov.b64 {%0, %1}, %2;" : "=f"(lo), "=f"(hi) : "l"(v));
}
__device__ __forceinline__ unsigned long long fma2(unsigned long long a,
                                                   unsigned long long b,
                                                   unsigned long long c) {
    unsigned long long d;
    asm("fma.rn.f32x2 %0, %1, %2, %3;" : "=l"(d) : "l"(a), "l"(b), "l"(c));
    return d;
}

// ================= kw: weight preprocessing (all-in-one) =================
__global__ void kw_pack(const float* __restrict__ w1, const float* __restrict__ w2,
                        const float* __restrict__ wl) {
    int gid = blockIdx.x * blockDim.x + threadIdx.x;
    int stride = gridDim.x * blockDim.x;
    // conv1 duplicated-weight staging
    for (int i = gid; i < C1 * 26; i += stride) {
        int c = i / 26, p = i % 26;
        float v = (p < 25) ? w1[c * 25 + p] : 0.f;
        g_swd_stage[i] = pack2(v, v);
    }
    // conv2 packed positive masks: {W3 = m0|m1<<20|m2<<40, W2 = m3|m4<<20} per (oc,ky)
    for (int i = gid; i < C2 * 5; i += stride) {
        int oc = i / 5, ky = i % 5;
        unsigned m[5];
        for (int kx = 0; kx < 5; kx++) {
            unsigned wp = 0;
            for (int ic = 0; ic < C1; ic++)
                if (w2[(oc * C1 + ic) * 25 + ky * 5 + kx] > 0.f) wp |= (1u << ic);
            m[kx] = wp;
        }
        ulonglong2 v;
        v.x = (unsigned long long)m[0] | ((unsigned long long)m[1] << 20)
            | ((unsigned long long)m[2] << 40);
        v.y = (unsigned long long)m[3] | ((unsigned long long)m[4] << 20);
        g_w2pk[i] = v;
    }
    // linear sign bitmask
    for (int i = gid; i < LIN_OUT * NWRD; i += stride) {
        int oc = i / NWRD, w = i % NWRD;
        unsigned bits = 0;
        for (int j = 0; j < 32; j++) {
            int k = w * 32 + j;
            if (k < LIN_IN && wl[oc * LIN_IN + k] > 0.f) bits |= (1u << j);
        }
        g_wpl[i] = bits;
    }
    // alpha: one warp per output row
    for (int i = gid; i < LIN_OUT * 32; i += stride) {
        int oc = i >> 5, lane = i & 31;
        float s = 0.f;
        for (int k = lane; k < LIN_IN; k += 32) s += fabsf(wl[oc * LIN_IN + k]);
#pragma unroll
        for (int off = 16; off > 0; off >>= 1)
            s += __shfl_down_sync(0xffffffffu, s, off);
        if (lane == 0) g_alphal[oc] = s * (1.f / (float)LIN_IN);
    }
}

// ================= k1: per-image conv1 channel sums via window sums =================
__global__ void k1_stats(const float* __restrict__ x, const float* __restrict__ w1) {
    int img = blockIdx.x, t = threadIdx.x;         // 256 threads
    __shared__ float sR[32 * 5];
    __shared__ float sS[25];
    __shared__ float sw[C1 * 25];
    for (int i = t; i < C1 * 25; i += 256) sw[i] = w1[i];
    int warp = t >> 5, lane = t & 31;
    for (int r = warp; r < 32; r += 8) {
        float v = x[img * 1024 + r * 32 + lane];
        float p = v;
#pragma unroll
        for (int off = 1; off < 32; off <<= 1) {
            float o = __shfl_up_sync(0xffffffffu, p, off);
            if (lane >= off) p += o;
        }
        float lo = __shfl_up_sync(0xffffffffu, p, 1);
        if (lane == 0) lo = 0.f;
        float hi = __shfl_sync(0xffffffffu, p, (lane + 27) & 31);
        if (lane < 5) sR[r * 5 + lane] = hi - lo;
    }
    __syncthreads();
    if (t < 25) {
        int ky = t / 5, kx = t % 5;
        float s = 0.f;
        for (int r = ky; r < ky + 28; r++) s += sR[r * 5 + kx];
        sS[t] = s;
    }
    __syncthreads();
    if (t < C1) {
        float a = 0.f;
#pragma unroll
        for (int p = 0; p < 25; p++) a += sw[t * 25 + p] * sS[p];
        g_part[img * C1 + t] = a;
    }
}

// ================= k2: deterministic channel-mean reduction =================
__global__ void k2_mean() {
    int c = blockIdx.x, t = threadIdx.x;
    __shared__ float red[256];
    float s = 0.f;
    for (int i = t; i < NIMG; i += 256) s += g_part[i * C1 + c];
    red[t] = s;
    __syncthreads();
    for (int o = 128; o > 0; o >>= 1) {
        if (t < o) red[t] += red[t + o];
        __syncthreads();
    }
    if (t == 0) g_mean[c] = red[0] * (1.0f / (8192.f * 784.f));
}

// ================= k3: conv1 + threshold + pool + sign (R8 best config) =================
#define K3_T 416
__global__ void __launch_bounds__(K3_T, 3) k3_conv1(const float* __restrict__ x) {
    __shared__ float sx[2048];               // 2 images
    int t = threadIdx.x;
    int base = blockIdx.x * 2048;
    for (int i = t; i < 2048; i += K3_T) sx[i] = x[base + i];
    __syncthreads();
    if (t < 392) {
        int il = t / 196, pp = t % 196;
        int py = pp / 14, px = pp % 14;
        const float* sxi = sx + il * 1024;
        // packed pairs: P[r][k] = (win[r][k], win[r][k+1])  — positions dx=0 / dx=1
        unsigned long long P[6][5];
#pragma unroll
        for (int r = 0; r < 6; r++) {
            float c0 = sxi[(py * 2 + r) * 32 + px * 2 + 0];
            float c1 = sxi[(py * 2 + r) * 32 + px * 2 + 1];
            float c2 = sxi[(py * 2 + r) * 32 + px * 2 + 2];
            float c3 = sxi[(py * 2 + r) * 32 + px * 2 + 3];
            float c4 = sxi[(py * 2 + r) * 32 + px * 2 + 4];
            float c5 = sxi[(py * 2 + r) * 32 + px * 2 + 5];
            P[r][0] = pack2(c0, c1);
            P[r][1] = pack2(c1, c2);
            P[r][2] = pack2(c2, c3);
            P[r][3] = pack2(c3, c4);
            P[r][4] = pack2(c4, c5);
        }
        unsigned int bits = 0;
#pragma unroll
        for (int c = 0; c < C1; c++) {
            const ulonglong2* wc2 = reinterpret_cast<const ulonglong2*>(&c_swd[c * 26]);
            unsigned long long a0 = 0ull, a1 = 0ull;   // dy=0 / dy=1, dx in halves
#pragma unroll
            for (int q = 0; q < 12; q++) {
                ulonglong2 w = wc2[q];
                int p0 = 2 * q, p1 = 2 * q + 1;
                a0 = fma2(P[p0 / 5][p0 % 5], w.x, a0);
                a1 = fma2(P[p0 / 5 + 1][p0 % 5], w.x, a1);
                a0 = fma2(P[p1 / 5][p1 % 5], w.y, a0);
                a1 = fma2(P[p1 / 5 + 1][p1 % 5], w.y, a1);
            }
            {
                unsigned long long w24 = c_swd[c * 26 + 24];
                a0 = fma2(P[4][4], w24, a0);
                a1 = fma2(P[5][4], w24, a1);
            }
            float f00, f01, f10, f11;
            unpack2(a0, f00, f01);
            unpack2(a1, f10, f11);
            float m = fmaxf(fmaxf(f00, f01), fmaxf(f10, f11));
            if (m > c_mean[c]) bits |= (1u << c);
        }
        g_b1p[(blockIdx.x * 2 + il) * P1PIX + pp] = bits;
    }
}

// ================= k4: XNOR conv2 + pool + sign, 64-bit packed popcount =================
__global__ void __launch_bounds__(256) k4_conv2() {
    __shared__ __align__(8) unsigned int sb[P1PIX];
    __shared__ __align__(16) ulonglong2 swk[C2 * 5];   // {W3, W2} per (oc,ky), 4KB
    __shared__ int spc[P1PIX];
    __shared__ int sS[100];
    __shared__ signed char s2b[1280];
    int img = blockIdx.x, t = threadIdx.x;
    for (int i = t; i < P1PIX; i += 256) {
        unsigned v = g_b1p[img * P1PIX + i];
        sb[i] = v;
        spc[i] = __popc(v);
    }
    for (int i = t; i < C2 * 5; i += 256) swk[i] = g_w2pk[i];
    __syncthreads();
    if (t < 100) {
        int py = t / 10, px = t % 10;
        int s = 0;
#pragma unroll
        for (int ky = 0; ky < 5; ky++)
#pragma unroll
            for (int kx = 0; kx < 5; kx++)
                s += spc[(py + ky) * 14 + px + kx];
        sS[t] = s;
    }
    __syncthreads();
    if (t < 250) {
        int pp = t / 10, ocg = t % 10;       // pixel pp cached across 5 ocs
        int py = pp / 5, px = pp % 5;
        // packed window rows: fields at bit offsets 0/20/40 (masks are 20-bit)
        unsigned long long Q0[6], Q1[6], T0[6], T1[6];
#pragma unroll
        for (int r = 0; r < 6; r++) {
            const uint2* row = reinterpret_cast<const uint2*>(sb + (py * 2 + r) * 14 + px * 2);
            uint2 v0 = row[0], v1 = row[1], v2 = row[2];
            unsigned long long w0 = v0.x, w1 = v0.y, w2 = v1.x;
            unsigned long long w3 = v1.y, w4 = v2.x, w5 = v2.y;
            Q0[r] = w0 | (w1 << 20) | (w2 << 40);   // dx=0, taps kx=0..2
            Q1[r] = w1 | (w2 << 20) | (w3 << 40);   // dx=1, taps kx=0..2
            T0[r] = w3 | (w4 << 20);                // dx=0, taps kx=3,4
            T1[r] = w4 | (w5 << 20);                // dx=1, taps kx=3,4
        }
        int b00 = sS[(2 * py) * 10 + 2 * px];
        int b01 = sS[(2 * py) * 10 + 2 * px + 1];
        int b10 = sS[(2 * py + 1) * 10 + 2 * px];
        int b11 = sS[(2 * py + 1) * 10 + 2 * px + 1];
#pragma unroll 1
        for (int j = 0; j < 5; j++) {
            int oc = ocg * 5 + j;
            const ulonglong2* wk = &swk[oc * 5];
            int A0 = 0, A1 = 0, A2 = 0, A3 = 0;
#pragma unroll
            for (int ky = 0; ky < 5; ky++) {
                ulonglong2 w = wk[ky];
                A0 += __popcll(Q0[ky]     & w.x) + __popcll(T0[ky]     & w.y);
                A1 += __popcll(Q1[ky]     & w.x) + __popcll(T1[ky]     & w.y);
                A2 += __popcll(Q0[ky + 1] & w.x) + __popcll(T0[ky + 1] & w.y);
                A3 += __popcll(Q1[ky + 1] & w.x) + __popcll(T1[ky + 1] & w.y);
            }
            int a0 = 2 * A0 - b00;
            int a1 = 2 * A1 - b01;
            int a2 = 2 * A2 - b10;
            int a3 = 2 * A3 - b11;
            int best = max(max(a0, a1), max(a2, a3));
            s2b[oc * 25 + pp] = (signed char)((best > 0) - (best < 0));
        }
    }
    for (int i = 1250 + t; i < 1280; i += 256) s2b[i] = 0;
    __syncthreads();
    int lane = t & 31;
#pragma unroll
    for (int it = 0; it < 5; it++) {
        int idx = it * 256 + t;
        int v = s2b[idx];
        unsigned bp = __ballot_sync(0xffffffffu, v > 0);
        unsigned bn = __ballot_sync(0xffffffffu, v < 0);
        if (lane == 0) g_s2p[img * NWRD + (idx >> 5)] = make_uint2(bp, bn);
    }
}

// ================= k5: popcount ternary linear + alpha + clip + fused fc =================
__global__ void __launch_bounds__(256) k5_linear(const float* __restrict__ fcw,
                                                 const float* __restrict__ fcb,
                                                 float* __restrict__ out) {
    __shared__ __align__(16) uint4 s2[IMGB * (NWRD / 2)];  // {sp_w, sn_w, sp_w+1, sn_w+1}
    __shared__ int   sD[IMGB];            // PSP - PSN per image
    __shared__ float sa[IMGB * LIN_OUT];  // clipped activations, 32 KB
    int blk = blockIdx.x, t = threadIdx.x;
    int n0 = blk * IMGB;
    const uint4* src = reinterpret_cast<const uint4*>(g_s2p + (size_t)n0 * NWRD);
    for (int i = t; i < IMGB * (NWRD / 2); i += 256) s2[i] = src[i];
    __syncthreads();
    if (t < IMGB) {
        int d = 0;
#pragma unroll
        for (int w = 0; w < NWRD / 2; w++) {
            uint4 s = s2[t * (NWRD / 2) + w];
            d += (__popc(s.x) - __popc(s.y)) + (__popc(s.z) - __popc(s.w));
        }
        sD[t] = d;
    }
    __syncthreads();
    for (int oc = t; oc < LIN_OUT; oc += 256) {
        float al = g_alphal[oc];
        const uint2* wr = reinterpret_cast<const uint2*>(g_wpl + oc * NWRD);
        int acc[IMGB];
#pragma unroll
        for (int n = 0; n < IMGB; n++) acc[n] = 0;
#pragma unroll 2
        for (int w = 0; w < NWRD / 2; w++) {
            uint2 wv = wr[w];
#pragma unroll
            for (int n = 0; n < IMGB; n++) {
                uint4 s = s2[n * (NWRD / 2) + w];
                acc[n] += (__popc(s.x & wv.x) - __popc(s.y & wv.x))
                        + (__popc(s.z & wv.y) - __popc(s.w & wv.y));
            }
        }
#pragma unroll
        for (int n = 0; n < IMGB; n++) {
            float v = (float)(2 * acc[n] - sD[n]) * al;
            v = fminf(1.f, fmaxf(-1.f, v));
            sa[n * LIN_OUT + oc] = v;
        }
    }
    __syncthreads();
    // fused fc: 16 images x 10 classes
    for (int i = t; i < IMGB * NCLS; i += 256) {
        int n = i / NCLS, cls = i % NCLS;
        const float* a = sa + n * LIN_OUT;
        const float* w = fcw + cls * LIN_OUT;
        float acc = 0.f;
#pragma unroll 4
        for (int k = 0; k < LIN_OUT; k++) acc += a[k] * w[k];
        out[(n0 + n) * NCLS + cls] = acc + fcb[cls];
    }
}

// ================= launch =================
extern "C" void kernel_launch(void* const* d_in, const int* in_sizes, int n_in,
                              void* d_out, int out_size) {
    const float* x   = (const float*)d_in[0];
    const float* w1  = (const float*)d_in[1];
    const float* w2  = (const float*)d_in[2];
    const float* wl  = (const float*)d_in[3];
    const float* fcw = (const float*)d_in[4];
    const float* fcb = (const float*)d_in[5];
    float* out = (float*)d_out;

    kw_pack  <<<256, 256>>>(w1, w2, wl);
    k1_stats <<<NIMG, 256>>>(x, w1);
    k2_mean  <<<C1, 256>>>();

    // stage -> constant memory (graph-capturable D2D memcpy nodes)
    void* p_swd = nullptr;
    void* p_mean = nullptr;
    cudaGetSymbolAddress(&p_swd, g_swd_stage);
    cudaGetSymbolAddress(&p_mean, g_mean);
    cudaMemcpyToSymbolAsync(c_swd, p_swd, C1 * 26 * sizeof(unsigned long long), 0,
                            cudaMemcpyDeviceToDevice, 0);
    cudaMemcpyToSymbolAsync(c_mean, p_mean, C1 * sizeof(float), 0,
                            cudaMemcpyDeviceToDevice, 0);

    k3_conv1 <<<NIMG / 2, K3_T>>>(x);
    k4_conv2 <<<NIMG, 256>>>();
    k5_linear<<<NIMG / IMGB, 256>>>(fcw, fcb, out);
}